// round 17
// baseline (speedup 1.0000x reference)
#include <cuda_runtime.h>
#include <cuda_fp16.h>
#include <cstdint>

// out[b,n,m,0]=cos(src_n,tgt_m), out[b,n,m,1]=1/(1+||src_n-tgt_m||)
// dot via 2-pass split-fp16 mma.sync: hiA*hiB + hiA*loB, fp32 accumulate.
// NO smem / NO barriers in main kernel: operands pre-packed into the exact
// mma.m16n8k16 per-lane fragment layout; loop = LDG.128(L2-resident) -> mma.

#define NN 2048
#define CC 128
#define ROWSZ (4 * NN)
#define NFRAG (512 * 8 * 32)   // 512 16-row tiles x 8 k-blocks x 32 lanes

__device__ __half g_hiS[ROWSZ * CC];
__device__ __half g_hiT[ROWSZ * CC];
__device__ __half g_loT[ROWSZ * CC];
__device__ float2 g_nS[ROWSZ];   // {|s|^2, 1/max(|s|,eps)}
__device__ float2 g_nT[ROWSZ];
// fragment-packed operands (16B per lane per (tile16, kb))
__device__ uint4 g_Af[NFRAG];    // src hi, A-frag order  {klo_r, klo_r8, khi_r, khi_r8}
__device__ uint4 g_Bh[NFRAG];    // tgt hi, B-frag order  {klo_r, khi_r, klo_r8, khi_r8}
__device__ uint4 g_Bl[NFRAG];    // tgt lo, B-frag order

// ---------------------------------------------------------------------------
// prep: fp32 -> fp16 hi (+ lo for tgt only) + fused row norms. Warp per row.
// ---------------------------------------------------------------------------
__global__ void prep(const float* __restrict__ S, const float* __restrict__ T) {
    int gw = (blockIdx.x * blockDim.x + threadIdx.x) >> 5;
    int lane = threadIdx.x & 31;
    if (gw >= ROWSZ) return;
    bool ist = (blockIdx.y != 0);
    const float* p = (ist ? T : S) + (size_t)gw * CC + lane * 4;
    float4 v = *(const float4*)p;
    float sq = v.x * v.x + v.y * v.y + v.z * v.z + v.w * v.w;
#pragma unroll
    for (int o = 16; o; o >>= 1) sq += __shfl_xor_sync(0xffffffffu, sq, o);

    __half2 h01 = __floats2half2_rn(v.x, v.y);
    __half2 h23 = __floats2half2_rn(v.z, v.w);

    size_t off = (size_t)gw * CC + lane * 4;
    if (ist) {
        float2 f01 = __half22float2(h01);
        float2 f23 = __half22float2(h23);
        __half2 l01 = __floats2half2_rn(v.x - f01.x, v.y - f01.y);
        __half2 l23 = __floats2half2_rn(v.z - f23.x, v.w - f23.y);
        *(uint2*)(g_hiT + off) = make_uint2(*(uint32_t*)&h01, *(uint32_t*)&h23);
        *(uint2*)(g_loT + off) = make_uint2(*(uint32_t*)&l01, *(uint32_t*)&l23);
    } else {
        *(uint2*)(g_hiS + off) = make_uint2(*(uint32_t*)&h01, *(uint32_t*)&h23);
    }
    if (lane == 0) {
        float2 nv;
        nv.x = sq;
        nv.y = 1.0f / fmaxf(sqrtf(sq), 1e-12f);
        (ist ? g_nT : g_nS)[gw] = nv;
    }
}

// ---------------------------------------------------------------------------
// repack: row-major half arrays -> mma fragment order.
// Thread t handles (tile rb, k-block kb, lane): one 16B output.
// A-frag regs:  a0=(row,klo) a1=(row+8,klo) a2=(row,khi) a3=(row+8,khi)
// B-frag regs:  b0=(row,klo) b1=(row,khi) b2=(row+8,klo) b3=(row+8,khi)
// where row = rb*16 + (lane>>2), klo word = kb*8 + (lane&3), khi = +4 words.
// ---------------------------------------------------------------------------
__global__ void repack() {
    int t = blockIdx.x * 256 + threadIdx.x;     // 0 .. NFRAG-1
    int lane = t & 31, kb = (t >> 5) & 7, rb = t >> 8;
    int row0 = rb * 16 + (lane >> 2);
    int c0 = kb * 8 + (lane & 3);
    int y = blockIdx.y;
    const uint32_t* u = (y == 0) ? (const uint32_t*)g_hiS
                      : (y == 1) ? (const uint32_t*)g_hiT
                                 : (const uint32_t*)g_loT;
    uint32_t w00 = u[row0 * 64 + c0];
    uint32_t w01 = u[row0 * 64 + c0 + 4];
    uint32_t w10 = u[(row0 + 8) * 64 + c0];
    uint32_t w11 = u[(row0 + 8) * 64 + c0 + 4];
    if (y == 0)      g_Af[t] = make_uint4(w00, w10, w01, w11);
    else if (y == 1) g_Bh[t] = make_uint4(w00, w01, w10, w11);
    else             g_Bl[t] = make_uint4(w00, w01, w10, w11);
}

// ---------------------------------------------------------------------------
__device__ __forceinline__ void mma16816(float* c, const uint32_t* a, const uint32_t* b) {
    asm volatile(
        "mma.sync.aligned.m16n8k16.row.col.f32.f16.f16.f32 "
        "{%0,%1,%2,%3}, {%4,%5,%6,%7}, {%8,%9}, {%0,%1,%2,%3};"
        : "+f"(c[0]), "+f"(c[1]), "+f"(c[2]), "+f"(c[3])
        : "r"(a[0]), "r"(a[1]), "r"(a[2]), "r"(a[3]), "r"(b[0]), "r"(b[1]));
}
__device__ __forceinline__ float sqrt_ap(float x) { float r; asm("sqrt.approx.f32 %0,%1;" : "=f"(r) : "f"(x)); return r; }
__device__ __forceinline__ float rcp_ap(float x)  { float r; asm("rcp.approx.f32 %0,%1;"  : "=f"(r) : "f"(x)); return r; }

// ---------------------------------------------------------------------------
// CTA tile 128(n) x 128(m), 8 warps 2(n) x 4(m), warp tile 64x32.
// K in 8 blocks of 16. Per kk/warp: 8 LDG.128 (L2-hit) + 32 mma.
// A/Bh double-buffered one kb ahead; Bl single-buffered (issued at kk top,
// consumed after the hi pass). Zero smem, zero barriers.
// ---------------------------------------------------------------------------
__global__ __launch_bounds__(256, 2)
void simgemm(float* __restrict__ out) {
    const int tid = threadIdx.x, lane = tid & 31, w = tid >> 5;
    const int wm = w & 1, wn = w >> 1;      // wm: n-dir (2), wn: m-dir (4)
    const int b = blockIdx.z, bm = blockIdx.x, bn = blockIdx.y;

    // fragment tile bases (16-row tiles over the 8192 global rows)
    const int rbBase = b * 128 + bn * 8 + wm * 4;   // A tiles (n), +mi
    const int pbBase = b * 128 + bm * 8 + wn * 2;   // B tiles (m), +nip
    const uint4* pA = g_Af + (size_t)rbBase * 256 + lane;  // +mi*256 +kb*32
    const uint4* pH = g_Bh + (size_t)pbBase * 256 + lane;  // +nip*256+kb*32
    const uint4* pL = g_Bl + (size_t)pbBase * 256 + lane;

    float acc[4][4][4];
#pragma unroll
    for (int i = 0; i < 4; i++)
#pragma unroll
        for (int j = 0; j < 4; j++)
#pragma unroll
            for (int k = 0; k < 4; k++) acc[i][j][k] = 0.0f;

    uint32_t A[2][4][4], BH[2][2][4], BL[2][4];

    // preload kb=0
#pragma unroll
    for (int mi = 0; mi < 4; mi++)
        *(uint4*)A[0][mi] = __ldg(pA + mi * 256);
#pragma unroll
    for (int nip = 0; nip < 2; nip++)
        *(uint4*)BH[0][nip] = __ldg(pH + nip * 256);

#pragma unroll
    for (int kk = 0; kk < 8; kk++) {
        const int cb = kk & 1, nb = cb ^ 1;
        // Bl for this kk (consumed after hi pass)
#pragma unroll
        for (int nip = 0; nip < 2; nip++)
            *(uint4*)BL[nip] = __ldg(pL + nip * 256 + kk * 32);
        // prefetch next kb
        if (kk < 7) {
#pragma unroll
            for (int mi = 0; mi < 4; mi++)
                *(uint4*)A[nb][mi] = __ldg(pA + mi * 256 + (kk + 1) * 32);
#pragma unroll
            for (int nip = 0; nip < 2; nip++)
                *(uint4*)BH[nb][nip] = __ldg(pH + nip * 256 + (kk + 1) * 32);
        }
        // hi x hi
#pragma unroll
        for (int mi = 0; mi < 4; mi++)
#pragma unroll
            for (int nip = 0; nip < 2; nip++) {
                mma16816(acc[mi][nip * 2],     A[cb][mi], &BH[cb][nip][0]);
                mma16816(acc[mi][nip * 2 + 1], A[cb][mi], &BH[cb][nip][2]);
            }
        // hi x lo
#pragma unroll
        for (int mi = 0; mi < 4; mi++)
#pragma unroll
            for (int nip = 0; nip < 2; nip++) {
                mma16816(acc[mi][nip * 2],     A[cb][mi], &BL[nip][0]);
                mma16816(acc[mi][nip * 2 + 1], A[cb][mi], &BL[nip][2]);
            }
    }

    // ---- epilogue ----
    const int q = lane >> 2;
    const int mp = (lane & 3) * 2;
#pragma unroll
    for (int mi = 0; mi < 4; mi++) {
        int n0 = bn * 128 + wm * 64 + mi * 16 + q;
        float2 ns0 = g_nS[b * NN + n0];
        float2 ns1 = g_nS[b * NN + n0 + 8];
        float* r0 = out + (((size_t)(b * NN + n0)) * NN) * 2;
        float* r1 = out + (((size_t)(b * NN + n0 + 8)) * NN) * 2;
#pragma unroll
        for (int ni = 0; ni < 4; ni++) {
            int m0 = bm * 128 + wn * 32 + ni * 8 + mp;
            float2 nt0 = g_nT[b * NN + m0];
            float2 nt1 = g_nT[b * NN + m0 + 1];
            const float* cc = acc[mi][ni];

            float cs00 = cc[0] * ns0.y * nt0.y;
            float cs01 = cc[1] * ns0.y * nt1.y;
            float cs10 = cc[2] * ns1.y * nt0.y;
            float cs11 = cc[3] * ns1.y * nt1.y;
            float fd00 = rcp_ap(1.0f + sqrt_ap(fmaxf(ns0.x + nt0.x - 2.0f * cc[0], 0.0f)));
            float fd01 = rcp_ap(1.0f + sqrt_ap(fmaxf(ns0.x + nt1.x - 2.0f * cc[1], 0.0f)));
            float fd10 = rcp_ap(1.0f + sqrt_ap(fmaxf(ns1.x + nt0.x - 2.0f * cc[2], 0.0f)));
            float fd11 = rcp_ap(1.0f + sqrt_ap(fmaxf(ns1.x + nt1.x - 2.0f * cc[3], 0.0f)));

            *(float4*)(r0 + (size_t)m0 * 2) = make_float4(cs00, fd00, cs01, fd01);
            *(float4*)(r1 + (size_t)m0 * 2) = make_float4(cs10, fd10, cs11, fd11);
        }
    }
}

// ---------------------------------------------------------------------------
extern "C" void kernel_launch(void* const* d_in, const int* in_sizes, int n_in,
                              void* d_out, int out_size) {
    const float* src = (const float*)d_in[0];
    const float* tgt = (const float*)d_in[1];
    float* out = (float*)d_out;
    (void)in_sizes; (void)n_in; (void)out_size;

    prep<<<dim3(1024, 2, 1), 256>>>(src, tgt);
    repack<<<dim3(512, 3, 1), 256>>>();
    simgemm<<<dim3(16, 16, 4), 256>>>(out);
}